// round 16
// baseline (speedup 1.0000x reference)
#include <cuda_runtime.h>
#include <cstdint>

// Scratch for the three bilinear outputs (with the appended ones column):
// g_o[m][b*64 + k], k in [0,63); column 63 == 1.0f.  3*512*64*4 = 384 KB.
__device__ __align__(16) float g_o[3][512 * 64];

// Per-64-batch-chunk completion flags (8 chunks of 64 b). Each chunk needs
// 63 k * 3 m = 189 item completions before outer_k may consume it.
__device__ unsigned int g_flag[8];

#define NUM_ITEMS   1512   // 8 chunks * 63 k * 3 m
#define ITEMS_PER_C 189
#define GRID1       592    // 4 blocks/SM * 148 SMs -> single wave (load-bearing for PDL)

// ---------- packed f32x2 helpers (Blackwell) ----------
__device__ __forceinline__ unsigned long long pk(float lo, float hi) {
    unsigned long long r;
    asm("mov.b64 %0, {%1, %2};" : "=l"(r) : "f"(lo), "f"(hi));
    return r;
}
__device__ __forceinline__ unsigned long long f2(unsigned long long a,
                                                 unsigned long long b,
                                                 unsigned long long c) {
    unsigned long long d;
    asm("fma.rn.f32x2 %0, %1, %2, %3;" : "=l"(d) : "l"(a), "l"(b), "l"(c));
    return d;
}
__device__ __forceinline__ void upk(unsigned long long v, float& lo, float& hi) {
    asm("mov.b64 {%0, %1}, %2;" : "=f"(lo), "=f"(hi) : "l"(v));
}

__global__ void reset_k() {
    if (threadIdx.x < 8) g_flag[threadIdx.x] = 0u;
}

// ---------------------------------------------------------------------------
// Stage 1 (persistent producer): o_m[b,k] = sum_ij A[b,i] W[k,i,j] C[b,j] + bias
// 592 blocks x 256 thr; thread = (bl = tid>>2 in [0,64), jq = tid&3 j-quarter).
// Item = (bchunk, k, m), bchunk-major so chunks complete in consumption order.
// W row padded to 80 floats in smem; A rows padded to 65. c2 = 8 f32x2 regs.
// Triggers programmatic launch completion at entry so outer_k starts at t~0.
// ---------------------------------------------------------------------------
__global__ __launch_bounds__(256, 5) void bilinear_pk(
    const float* __restrict__ x, const float* __restrict__ y,
    const float* __restrict__ z,
    const float* __restrict__ W1, const float* __restrict__ b1,
    const float* __restrict__ W2, const float* __restrict__ b2,
    const float* __restrict__ W3, const float* __restrict__ b3) {
#if __CUDA_ARCH__ >= 900
    cudaTriggerProgrammaticLaunchCompletion();
#endif
    __shared__ __align__(16) float Ws[64 * 80];   // 20.0 KB, row i at i*80
    __shared__ float As[64 * 65];                 // 16.25 KB, padded A rows

    const int tid = threadIdx.x;
    const int bl  = tid >> 2;     // local batch 0..63
    const int jq  = tid & 3;      // j quarter (16 j's)

    const float* Asel[3] = {x, x, y};
    const float* Csel[3] = {y, z, z};
    const float* Wsel[3] = {W1, W2, W3};
    const float* Bsel[3] = {b1, b2, b3};

    for (int it = blockIdx.x; it < NUM_ITEMS; it += GRID1) {
        const int bc = it / ITEMS_PER_C;
        const int r  = it - bc * ITEMS_PER_C;
        const int k  = r / 3;
        const int m  = r - k * 3;

        const float* A    = Asel[m];
        const float* C    = Csel[m];
        const float* W    = Wsel[m];
        const float* bias = Bsel[m];
        const int b = bc * 64 + bl;

        __syncthreads();  // previous item's smem reads complete

        // Stage W[k] (16 KB) into padded smem, float4-wide.
        {
            const float4* Wg = (const float4*)(W + (size_t)k * 4096);
            #pragma unroll
            for (int q = 0; q < 4; ++q) {
                int idx4 = tid + 256 * q;          // 0..1023
                float4 v = Wg[idx4];
                int i  = idx4 >> 4;
                int j4 = idx4 & 15;
                *(float4*)(Ws + i * 80 + j4 * 4) = v;
            }
        }
        // Stage this chunk's A rows (64 x 64), padded stride 65.
        {
            const float4* Ag = (const float4*)(A + (size_t)bc * 64 * 64);
            #pragma unroll
            for (int q = 0; q < 4; ++q) {
                int idx4 = tid + 256 * q;          // 0..1023
                float4 v = Ag[idx4];
                int row = idx4 >> 4;
                int col = (idx4 & 15) * 4;
                float* dst = As + row * 65 + col;
                dst[0] = v.x; dst[1] = v.y; dst[2] = v.z; dst[3] = v.w;
            }
        }

        // Pack this thread's 16-wide C quarter into 8 f32x2 registers.
        unsigned long long c2[8];
        {
            const float4* c4 = (const float4*)(C + (size_t)b * 64 + jq * 16);
            #pragma unroll
            for (int q = 0; q < 4; ++q) {
                float4 v = c4[q];
                c2[2 * q]     = pk(v.x, v.y);
                c2[2 * q + 1] = pk(v.z, v.w);
            }
        }
        __syncthreads();

        unsigned long long accA = 0ull, accB = 0ull;
        const float* arow = As + bl * 65;

        #pragma unroll 2
        for (int i = 0; i < 64; ++i) {
            const ulonglong2* wr = (const ulonglong2*)(Ws + i * 80 + jq * 16);
            unsigned long long sA = 0ull, sB = 0ull;
            #pragma unroll
            for (int q = 0; q < 4; ++q) {
                ulonglong2 w = wr[q];
                sA = f2(w.x, c2[2 * q],     sA);
                sB = f2(w.y, c2[2 * q + 1], sB);
            }
            float ai = arow[i];
            unsigned long long a2 = pk(ai, ai);
            accA = f2(a2, sA, accA);
            accB = f2(a2, sB, accB);
        }

        float la, ha, lb, hb;
        upk(accA, la, ha);
        upk(accB, lb, hb);
        float part = (la + ha) + (lb + hb);
        part += __shfl_xor_sync(0xffffffffu, part, 1);  // join j quarters
        part += __shfl_xor_sync(0xffffffffu, part, 2);

        if (jq == 0) {
            g_o[m][b * 64 + k] = part + bias[k];
            if (k == 0) g_o[m][b * 64 + 63] = 1.0f;     // appended ones column
        }

        __syncthreads();  // all stores of this item done
        if (tid == 0) {
            __threadfence();                             // release
            atomicAdd(&g_flag[bc], 1u);
        }
    }
}

// ---------------------------------------------------------------------------
// Stage 2 (PDL consumer): out[b, i*4096 + j*64 + k] = o1[b,i]*o2[b,j]*o3[b,k]
// grid (64 i, 512 b) -> b-major dispatch matches production order. Spins on
// the b-chunk flag, then 4 perfectly coalesced STG.128 per thread.
// ---------------------------------------------------------------------------
__global__ __launch_bounds__(256) void outer_k(float* __restrict__ out) {
    const int i = blockIdx.x;
    const int b = blockIdx.y;

    if (threadIdx.x == 0) {
        const volatile unsigned int* f = (const volatile unsigned int*)g_flag;
        while (f[b >> 6] < (unsigned)ITEMS_PER_C) __nanosleep(128);
        __threadfence();                                 // acquire
    }
    __syncthreads();

    const float* o1 = g_o[0] + b * 64;
    const float* o2 = g_o[1] + b * 64;
    const float* o3 = g_o[2] + b * 64;

    const float o1i = o1[i];
    const float4 w = ((const float4*)o3)[threadIdx.x & 15];

    float4* out4 = (float4*)out + (size_t)b * 65536 + (size_t)i * 1024;
    const int jb = threadIdx.x >> 4;

    #pragma unroll
    for (int u = 0; u < 4; ++u) {
        float v = o1i * o2[jb + 16 * u];
        float4 r;
        r.x = v * w.x;
        r.y = v * w.y;
        r.z = v * w.z;
        r.w = v * w.w;
        out4[threadIdx.x + 256 * u] = r;
    }
}

extern "C" void kernel_launch(void* const* d_in, const int* in_sizes, int n_in,
                              void* d_out, int out_size) {
    const float* x  = (const float*)d_in[0];
    const float* y  = (const float*)d_in[1];
    const float* z  = (const float*)d_in[2];
    const float* W1 = (const float*)d_in[3];
    const float* b1 = (const float*)d_in[4];
    const float* W2 = (const float*)d_in[5];
    const float* b2 = (const float*)d_in[6];
    const float* W3 = (const float*)d_in[7];
    const float* b3 = (const float*)d_in[8];
    float* out = (float*)d_out;

    reset_k<<<1, 32>>>();

    bilinear_pk<<<GRID1, 256>>>(x, y, z, W1, b1, W2, b2, W3, b3);

    // outer_k with programmatic dependent launch: starts while bilinear_pk is
    // still running (it triggered at entry); flags gate per-chunk consumption.
    cudaLaunchConfig_t cfg = {};
    cfg.gridDim  = dim3(64, 512);
    cfg.blockDim = dim3(256);
    cfg.dynamicSmemBytes = 0;
    cfg.stream = 0;
    cudaLaunchAttribute attr[1];
    attr[0].id = cudaLaunchAttributeProgrammaticStreamSerialization;
    attr[0].val.programmaticStreamSerializationAllowed = 1;
    cfg.attrs = attr;
    cfg.numAttrs = 1;
    cudaError_t e = cudaLaunchKernelEx(&cfg, outer_k, out);
    if (e != cudaSuccess) {
        // Fallback: plain serialized launch (correct, just no overlap).
        outer_k<<<dim3(64, 512), 256>>>(out);
    }
}

// round 17
// speedup vs baseline: 1.1903x; 1.1903x over previous
#include <cuda_runtime.h>
#include <cstdint>

// Scratch for the three bilinear outputs (with the appended ones column):
// g_o[m][b*64 + k], k in [0,63); column 63 == 1.0f.  3*512*64*4 = 384 KB.
__device__ __align__(16) float g_o[3][512 * 64];

// Per-64-batch-chunk flags, each on its own 128B line. Self-cleaning:
// producers count items up to 189; the last consumer block of a chunk resets.
struct __align__(128) PadCtr { unsigned int v; unsigned int pad[31]; };
__device__ PadCtr g_flag[8];
__device__ PadCtr g_done[8];

#define NUM_ITEMS     1512   // 8 chunks * 63 k * 3 m
#define ITEMS_PER_C   189
#define BLOCKS_PER_C  4096   // outer blocks per chunk: 64 b * 64 i
#define GRID1         444    // 3 blocks/SM * 148 SMs -> single wave; leaves
                             // 16K regs/SM free so outer_k co-resides (PDL).

// ---------- packed f32x2 helpers (Blackwell) ----------
__device__ __forceinline__ unsigned long long pk(float lo, float hi) {
    unsigned long long r;
    asm("mov.b64 %0, {%1, %2};" : "=l"(r) : "f"(lo), "f"(hi));
    return r;
}
__device__ __forceinline__ unsigned long long f2(unsigned long long a,
                                                 unsigned long long b,
                                                 unsigned long long c) {
    unsigned long long d;
    asm("fma.rn.f32x2 %0, %1, %2, %3;" : "=l"(d) : "l"(a), "l"(b), "l"(c));
    return d;
}
__device__ __forceinline__ void upk(unsigned long long v, float& lo, float& hi) {
    asm("mov.b64 {%0, %1}, %2;" : "=f"(lo), "=f"(hi) : "l"(v));
}

// ---------------------------------------------------------------------------
// Stage 1 (producer): o_m[b,k] = sum_ij A[b,i] W[k,i,j] C[b,j] + bias[k]
// 444 blocks x 256 thr; thread = (bl = tid>>2 in [0,64), jq = tid&3).
// Item = (bchunk, k, m), bchunk-major so chunks complete in consumption order.
// W row i lives at Ws[i*80], as 4 x 16-float quarters at +0/+20/+40/+60 ->
// the 4 jq broadcast groups hit disjoint bank quads (single-phase LDS.128).
// A chunk staged padded (stride 65). c2 = 8 f32x2 regs. <=64 regs (256,4).
// ---------------------------------------------------------------------------
__global__ __launch_bounds__(256, 4) void bilinear_pk(
    const float* __restrict__ x, const float* __restrict__ y,
    const float* __restrict__ z,
    const float* __restrict__ W1, const float* __restrict__ b1,
    const float* __restrict__ W2, const float* __restrict__ b2,
    const float* __restrict__ W3, const float* __restrict__ b3) {
#if __CUDA_ARCH__ >= 900
    cudaTriggerProgrammaticLaunchCompletion();
#endif
    __shared__ __align__(16) float Ws[64 * 80];   // 20.0 KB
    __shared__ float As[64 * 65];                 // 16.25 KB

    const int tid = threadIdx.x;
    const int bl  = tid >> 2;     // local batch 0..63
    const int jq  = tid & 3;      // j quarter (16 j's)

    for (int it = blockIdx.x; it < NUM_ITEMS; it += GRID1) {
        const int bc = it / ITEMS_PER_C;
        const int r  = it - bc * ITEMS_PER_C;
        const int k  = r / 3;
        const int m  = r - k * 3;

        const float* A;
        const float* C;
        const float* W;
        const float* bias;
        if (m == 0)      { A = x; C = y; W = W1; bias = b1; }
        else if (m == 1) { A = x; C = z; W = W2; bias = b2; }
        else             { A = y; C = z; W = W3; bias = b3; }
        const int b = bc * 64 + bl;

        __syncthreads();  // previous item's smem reads complete

        // Stage W[k] (16 KB), quarters padded: j4 -> (j4>>2)*20 + (j4&3)*4.
        {
            const float4* Wg = (const float4*)(W + (size_t)k * 4096);
            #pragma unroll
            for (int q = 0; q < 4; ++q) {
                int idx4 = tid + 256 * q;          // 0..1023
                float4 v = Wg[idx4];
                int i  = idx4 >> 4;
                int j4 = idx4 & 15;
                int off = (j4 >> 2) * 20 + (j4 & 3) * 4;
                *(float4*)(Ws + i * 80 + off) = v;
            }
        }
        // Stage this chunk's A rows (64 x 64), padded stride 65.
        {
            const float4* Ag = (const float4*)(A + (size_t)bc * 64 * 64);
            #pragma unroll
            for (int q = 0; q < 4; ++q) {
                int idx4 = tid + 256 * q;          // 0..1023
                float4 v = Ag[idx4];
                int row = idx4 >> 4;
                int col = (idx4 & 15) * 4;
                float* dst = As + row * 65 + col;
                dst[0] = v.x; dst[1] = v.y; dst[2] = v.z; dst[3] = v.w;
            }
        }

        // Pack this thread's 16-wide C quarter into 8 f32x2 registers.
        unsigned long long c2[8];
        {
            const float4* c4 = (const float4*)(C + (size_t)b * 64 + jq * 16);
            #pragma unroll
            for (int q = 0; q < 4; ++q) {
                float4 v = c4[q];
                c2[2 * q]     = pk(v.x, v.y);
                c2[2 * q + 1] = pk(v.z, v.w);
            }
        }
        __syncthreads();

        unsigned long long accA = 0ull, accB = 0ull;
        const float* arow = As + bl * 65;
        const int joff = jq * 20;

        #pragma unroll 2
        for (int i = 0; i < 64; ++i) {
            const ulonglong2* wr = (const ulonglong2*)(Ws + i * 80 + joff);
            unsigned long long sA = 0ull, sB = 0ull;
            #pragma unroll
            for (int q = 0; q < 4; ++q) {
                ulonglong2 w = wr[q];
                sA = f2(w.x, c2[2 * q],     sA);
                sB = f2(w.y, c2[2 * q + 1], sB);
            }
            float ai = arow[i];
            unsigned long long a2 = pk(ai, ai);
            accA = f2(a2, sA, accA);
            accB = f2(a2, sB, accB);
        }

        float la, ha, lb, hb;
        upk(accA, la, ha);
        upk(accB, lb, hb);
        float part = (la + ha) + (lb + hb);
        part += __shfl_xor_sync(0xffffffffu, part, 1);  // join j quarters
        part += __shfl_xor_sync(0xffffffffu, part, 2);

        if (jq == 0) {
            g_o[m][b * 64 + k] = part + bias[k];
            if (k == 0) g_o[m][b * 64 + 63] = 1.0f;     // appended ones column
        }

        __syncthreads();  // all stores of this item done
        if (tid == 0) {
            __threadfence();                             // release
            atomicAdd(&g_flag[bc].v, 1u);
        }
    }
}

// ---------------------------------------------------------------------------
// Stage 2 (PDL consumer): out[b, i*4096 + j*64 + k] = o1[b,i]*o2[b,j]*o3[b,k]
// grid (64 i, 512 b): b-major dispatch matches production order. Spins on
// the b-chunk flag, then 4 perfectly coalesced STG.128 per thread. The last
// block of each chunk resets the chunk's counters (clean state every run).
// ---------------------------------------------------------------------------
__global__ __launch_bounds__(256) void outer_k(float* __restrict__ out) {
    const int i  = blockIdx.x;
    const int b  = blockIdx.y;
    const int bc = b >> 6;

    if (threadIdx.x == 0) {
        volatile unsigned int* f = &g_flag[bc].v;
        while (*f < (unsigned)ITEMS_PER_C) __nanosleep(64);
        __threadfence();                                 // acquire
    }
    __syncthreads();

    const float* o1 = g_o[0] + b * 64;
    const float* o2 = g_o[1] + b * 64;
    const float* o3 = g_o[2] + b * 64;

    const float o1i = o1[i];
    const float4 w = ((const float4*)o3)[threadIdx.x & 15];

    float4* out4 = (float4*)out + (size_t)b * 65536 + (size_t)i * 1024;
    const int jb = threadIdx.x >> 4;

    #pragma unroll
    for (int u = 0; u < 4; ++u) {
        float v = o1i * o2[jb + 16 * u];
        float4 r;
        r.x = v * w.x;
        r.y = v * w.y;
        r.z = v * w.z;
        r.w = v * w.w;
        out4[threadIdx.x + 256 * u] = r;
    }

    // Self-cleaning flags: count blocks that PASSED the wait; the 4096th
    // resets both counters for the next graph replay. No waiter can observe
    // the reset early (it has already incremented only after passing).
    if (threadIdx.x == 0) {
        unsigned int d = atomicAdd(&g_done[bc].v, 1u);
        if (d == (unsigned)(BLOCKS_PER_C - 1)) {
            atomicExch(&g_flag[bc].v, 0u);
            atomicExch(&g_done[bc].v, 0u);
        }
    }
}

extern "C" void kernel_launch(void* const* d_in, const int* in_sizes, int n_in,
                              void* d_out, int out_size) {
    const float* x  = (const float*)d_in[0];
    const float* y  = (const float*)d_in[1];
    const float* z  = (const float*)d_in[2];
    const float* W1 = (const float*)d_in[3];
    const float* b1 = (const float*)d_in[4];
    const float* W2 = (const float*)d_in[5];
    const float* b2 = (const float*)d_in[6];
    const float* W3 = (const float*)d_in[7];
    const float* b3 = (const float*)d_in[8];
    float* out = (float*)d_out;

    bilinear_pk<<<GRID1, 256>>>(x, y, z, W1, b1, W2, b2, W3, b3);

    // outer_k with programmatic dependent launch: starts while bilinear_pk is
    // still running (it triggers at entry); flags gate per-chunk consumption.
    cudaLaunchConfig_t cfg = {};
    cfg.gridDim  = dim3(64, 512);
    cfg.blockDim = dim3(256);
    cfg.dynamicSmemBytes = 0;
    cfg.stream = 0;
    cudaLaunchAttribute attr[1];
    attr[0].id = cudaLaunchAttributeProgrammaticStreamSerialization;
    attr[0].val.programmaticStreamSerializationAllowed = 1;
    cfg.attrs = attr;
    cfg.numAttrs = 1;
    cudaError_t e = cudaLaunchKernelEx(&cfg, outer_k, out);
    if (e != cudaSuccess) {
        // Fallback: plain serialized launch (only taken if the EX launch did
        // not happen; correct, just without overlap).
        outer_k<<<dim3(64, 512), 256>>>(out);
    }
}